// round 16
// baseline (speedup 1.0000x reference)
#include <cuda_runtime.h>
#include <math.h>
#include <stdint.h>

typedef unsigned long long ull;

#define BATCH 64
#define SEQ   2048
#define IN_F  256
#define HID   512
#define RANKS 8     // CTAs per cluster; each owns 64 columns of W_hh
#define BPC   4     // batch rows per cluster

// 32 regions (one per k-lane) x 16 entries x 16B payload, stride 272 so the
// 32 lanes' concurrent reads are bank-conflict-free (bank = 4(lane+c) mod 32).
#define REG_STR   272
#define BUF_B     (32 * REG_STR)        // 8704 per buffer

// ---------------------------------------------------------------------------
// Packed f32x2 helpers
// ---------------------------------------------------------------------------
__device__ __forceinline__ ull ffma2(ull a, ull b, ull c) {
    ull d;
    asm("fma.rn.f32x2 %0, %1, %2, %3;" : "=l"(d) : "l"(a), "l"(b), "l"(c));
    return d;
}
__device__ __forceinline__ ull addx2(ull a, ull b) {
    ull d;
    asm("add.rn.f32x2 %0, %1, %2;" : "=l"(d) : "l"(a), "l"(b));
    return d;
}
__device__ __forceinline__ ull dup2(float x) {
    ull d;
    asm("mov.b64 %0, {%1, %1};" : "=l"(d) : "f"(x));
    return d;
}
__device__ __forceinline__ ull pack2(float lo, float hi) {
    ull d;
    asm("mov.b64 %0, {%1, %2};" : "=l"(d) : "f"(lo), "f"(hi));
    return d;
}
__device__ __forceinline__ float f2lo(ull v) {
    return __int_as_float((int)(unsigned int)(v & 0xffffffffULL));
}
__device__ __forceinline__ float f2hi(ull v) {
    return __int_as_float((int)(unsigned int)(v >> 32));
}
__device__ __forceinline__ ull shfl_xor64(ull v, int m) {
    float lo = f2lo(v), hi = f2hi(v);
    lo = __shfl_xor_sync(0xffffffffu, lo, m);
    hi = __shfl_xor_sync(0xffffffffu, hi, m);
    return pack2(lo, hi);
}

// ---------------------------------------------------------------------------
// cluster primitives — store/flag transport (no mbarriers, no bulk engine)
// ---------------------------------------------------------------------------
// weak remote store: write u64 to same smem offset in cluster CTA r
__device__ __forceinline__ void st_cluster_u64(uint32_t saddr, int r, ull v) {
    uint32_t ra;
    asm volatile("mapa.shared::cluster.u32 %0, %1, %2;" : "=r"(ra) : "r"(saddr), "r"(r));
    asm volatile("st.shared::cluster.u64 [%0], %1;" :: "r"(ra), "l"(v) : "memory");
}
// release store of a u32 flag into cluster CTA r (publishes all prior stores
// ordered before it via the CTA barrier happens-before edge)
__device__ __forceinline__ void st_release_flag(uint32_t saddr, int r, uint32_t v) {
    uint32_t ra;
    asm volatile("mapa.shared::cluster.u32 %0, %1, %2;" : "=r"(ra) : "r"(saddr), "r"(r));
    asm volatile("st.release.cluster.shared::cluster.u32 [%0], %1;"
                 :: "r"(ra), "r"(v) : "memory");
}
// acquire load of a local flag (written remotely by a peer's release store)
__device__ __forceinline__ uint32_t ld_acquire_flag(uint32_t saddr) {
    uint32_t v;
    asm volatile("ld.acquire.cluster.shared::cta.u32 %0, [%1];"
                 : "=r"(v) : "r"(saddr) : "memory");
    return v;
}
__device__ __forceinline__ void cluster_sync_() {
    asm volatile("barrier.cluster.arrive.aligned;" ::: "memory");
    asm volatile("barrier.cluster.wait.aligned;" ::: "memory");
}

// ---------------------------------------------------------------------------
// Kernel 1: x_proj GEMM  out[m][n] = sum_k X[m][k]*Wih[n][k] + bih[n] + bhh[n]
// ---------------------------------------------------------------------------
#define BM 128
#define BN 64
#define BK 32
#define ASP 130

__global__ __launch_bounds__(256) void xproj_kernel(
    const float* __restrict__ X, const float* __restrict__ Wih,
    const float* __restrict__ bih, const float* __restrict__ bhh,
    float* __restrict__ out)
{
    __shared__ float As[BK][ASP];
    __shared__ float Ws[BK][BN];

    const int tid = threadIdx.x;
    const int m0 = blockIdx.x * BM;
    const int n0 = blockIdx.y * BN;
    const int tx = tid & 15;
    const int ty = tid >> 4;

    ull acc[4][4];
#pragma unroll
    for (int r = 0; r < 4; r++)
#pragma unroll
        for (int c = 0; c < 4; c++) acc[r][c] = 0ULL;

    for (int k0 = 0; k0 < IN_F; k0 += BK) {
#pragma unroll
        for (int i = 0; i < 4; i++) {
            int idx = tid + i * 256;
            int m = idx >> 3;
            int k4 = idx & 7;
            float4 v = *(const float4*)(X + (size_t)(m0 + m) * IN_F + k0 + k4 * 4);
            As[k4 * 4 + 0][m] = v.x;
            As[k4 * 4 + 1][m] = v.y;
            As[k4 * 4 + 2][m] = v.z;
            As[k4 * 4 + 3][m] = v.w;
        }
#pragma unroll
        for (int i = 0; i < 2; i++) {
            int idx = tid + i * 256;
            int n = idx >> 3;
            int k4 = idx & 7;
            float4 v = *(const float4*)(Wih + (size_t)(n0 + n) * IN_F + k0 + k4 * 4);
            Ws[k4 * 4 + 0][n] = v.x;
            Ws[k4 * 4 + 1][n] = v.y;
            Ws[k4 * 4 + 2][n] = v.z;
            Ws[k4 * 4 + 3][n] = v.w;
        }
        __syncthreads();

#pragma unroll
        for (int k = 0; k < BK; k++) {
            ull ap[4];
#pragma unroll
            for (int r = 0; r < 4; r++)
                ap[r] = *(const ull*)&As[k][ty * 8 + 2 * r];
            float4 wv = *(const float4*)&Ws[k][tx * 4];
            ull wd0 = dup2(wv.x), wd1 = dup2(wv.y);
            ull wd2 = dup2(wv.z), wd3 = dup2(wv.w);
#pragma unroll
            for (int r = 0; r < 4; r++) {
                acc[r][0] = ffma2(ap[r], wd0, acc[r][0]);
                acc[r][1] = ffma2(ap[r], wd1, acc[r][1]);
                acc[r][2] = ffma2(ap[r], wd2, acc[r][2]);
                acc[r][3] = ffma2(ap[r], wd3, acc[r][3]);
            }
        }
        __syncthreads();
    }

    float bsum[4];
#pragma unroll
    for (int c = 0; c < 4; c++) {
        int n = n0 + tx * 4 + c;
        bsum[c] = bih[n] + bhh[n];
    }
#pragma unroll
    for (int r = 0; r < 4; r++) {
        size_t mlo = (size_t)(m0 + ty * 8 + 2 * r);
        float4 lo4, hi4;
        lo4.x = f2lo(acc[r][0]) + bsum[0]; lo4.y = f2lo(acc[r][1]) + bsum[1];
        lo4.z = f2lo(acc[r][2]) + bsum[2]; lo4.w = f2lo(acc[r][3]) + bsum[3];
        hi4.x = f2hi(acc[r][0]) + bsum[0]; hi4.y = f2hi(acc[r][1]) + bsum[1];
        hi4.z = f2hi(acc[r][2]) + bsum[2]; hi4.w = f2hi(acc[r][3]) + bsum[3];
        *(float4*)(out + mlo * HID + n0 + tx * 4)       = lo4;
        *(float4*)(out + (mlo + 1) * HID + n0 + tx * 4) = hi4;
    }
}

// ---------------------------------------------------------------------------
// Kernel 2: cluster scan — R14 compute (4 cols/thread, conflict-free 272B
// regions, value-splitting butterfly) with STORE/FLAG transport:
//
//   * writers push their fresh 16B h-entry straight into all 7 peers' next
//     buffer with weak st.shared::cluster (issued pre-sync; flight overlaps
//     out-store + xp prefetch of other warps),
//   * one __syncthreads per step (closes reads of buf p, orders all stores),
//   * 7 threads each publish a MONOTONIC step counter to one peer via
//     st.release.cluster (release chains through the barrier h-b edge),
//   * receivers poll all 7 flags with a single warp-wide ld.acquire +
//     __all_sync ballot per warp — no step-start syncthreads, no mbarriers,
//     no bulk-DMA engine, no cluster fences anywhere in the loop.
//
// Flag protocol: flags[src] holds the last step src completed + 1 (i.e. the
// step whose input buffer src has fully populated in our smem). At step t a
// warp may read buf[t&1] once all flags >= t. A peer writes buf[1-p] at its
// step t only after seeing OUR flag >= t, which we publish only after the
// syncthreads that closed our step t-1 reads of buf[1-p] -> max skew 1 step.
// ---------------------------------------------------------------------------
__global__ void __cluster_dims__(RANKS, 1, 1) __launch_bounds__(512, 1)
scan_kernel(const float* __restrict__ h0, const float* __restrict__ Whh,
            float* __restrict__ out)
{
    __shared__ __align__(16) char hbuf[2 * BUF_B];
    __shared__ __align__(16) uint32_t flags[8];   // flags[src] from peer src

    const int tid  = threadIdx.x;
    const int lane = tid & 31;                 // k-chunk index
    const int grp  = tid >> 5;                 // warp id = column group
    const int rank = blockIdx.x & (RANKS - 1);
    const int cid  = blockIdx.x >> 3;
    const int b0   = cid * BPC;
    const int gcol0 = rank * 64 + 4 * grp;     // first of our 4 columns

    // ---- W slices: 4 cols x 16 ks
    float w[4][16];
#pragma unroll
    for (int c = 0; c < 4; c++) {
        const float* wr = Whh + (size_t)(gcol0 + c) * HID + lane * 16;
#pragma unroll
        for (int j4 = 0; j4 < 4; j4++) {
            float4 a = *(const float4*)(wr + j4 * 4);
            w[c][4*j4+0] = a.x; w[c][4*j4+1] = a.y;
            w[c][4*j4+2] = a.z; w[c][4*j4+3] = a.w;
        }
    }

    if (tid < 8) flags[tid] = 0;

    // ---- preload h0 into buffer 0 (k = tid)
    {
        const int k = tid;
        float v0 = h0[(size_t)(b0 + 0) * HID + k];
        float v1 = h0[(size_t)(b0 + 1) * HID + k];
        float v2 = h0[(size_t)(b0 + 2) * HID + k];
        float v3 = h0[(size_t)(b0 + 3) * HID + k];
        char* e = hbuf + (k >> 4) * REG_STR + (k & 15) * 16;
        *(ull*)e       = pack2(v0, v1);
        *(ull*)(e + 8) = pack2(v2, v3);
    }
    __syncthreads();
    cluster_sync_();            // flags zeroed + buffer0 visible cluster-wide

    const uint32_t hpb = (uint32_t)__cvta_generic_to_shared(hbuf);
    const uint32_t flb = (uint32_t)__cvta_generic_to_shared(flags);

    // final-lane roles (after butterfly)
    const int  fcol = (lane >> 3) & 3;              // col within group
    const int  fbp  = (lane >> 2) & 1;              // batch pair
    const bool outl = (lane & 2) == 0;
    const int  obat = 2 * fbp + (lane & 1);
    const size_t obase = outl
        ? (((size_t)(b0 + obat) * SEQ) * HID + gcol0 + fcol) : 0;
    float xpv = outl ? out[obase] : 0.0f;

    const bool writer = (lane & 7) == 0;            // lanes 0,8,16,24
    // poll role: lanes 0..7 check flags[lane]; own rank always ready
    const bool pollme = (lane < 8) && (lane != rank);
    const uint32_t myflag = flb + (uint32_t)(lane * 4);

    for (int t = 0; t < SEQ; t++) {
        const int p = t & 1;

        // ---- wait for all 7 source regions of buf p (warp-local poll)
        if (t) {
            const uint32_t tt = (uint32_t)t;
            for (;;) {
                uint32_t f = 0xffffffffu;
                if (pollme) f = ld_acquire_flag(myflag);
                if (__all_sync(0xffffffffu, f >= tt)) break;
            }
        }

        const ulonglong2* hreg =
            (const ulonglong2*)(hbuf + p * BUF_B + lane * REG_STR);
        ull a01[4] = {0, 0, 0, 0};
        ull a23[4] = {0, 0, 0, 0};
#pragma unroll
        for (int j = 0; j < 16; j++) {
            ulonglong2 e = hreg[j];
#pragma unroll
            for (int c = 0; c < 4; c++) {
                ull wd = dup2(w[c][j]);
                a01[c] = ffma2(wd, e.x, a01[c]);
                a23[c] = ffma2(wd, e.y, a23[c]);
            }
        }

        // prefetch next step's xp while reduction/exchange runs
        float xpn = 0.0f;
        if (outl && t + 1 < SEQ) xpn = out[obase + (size_t)(t + 1) * HID];

        // ---- value-splitting butterfly over the full warp
        const bool hi16 = (lane & 16) != 0;
        ull s0 = hi16 ? a01[2] : a01[0];
        ull s1 = hi16 ? a23[2] : a23[0];
        ull s2 = hi16 ? a01[3] : a01[1];
        ull s3 = hi16 ? a23[3] : a23[1];
        s0 = addx2(s0, shfl_xor64(hi16 ? a01[0] : a01[2], 16));
        s1 = addx2(s1, shfl_xor64(hi16 ? a23[0] : a23[2], 16));
        s2 = addx2(s2, shfl_xor64(hi16 ? a01[1] : a01[3], 16));
        s3 = addx2(s3, shfl_xor64(hi16 ? a23[1] : a23[3], 16));
        const bool hi8 = (lane & 8) != 0;
        ull t0 = hi8 ? s2 : s0;
        ull t1 = hi8 ? s3 : s1;
        t0 = addx2(t0, shfl_xor64(hi8 ? s0 : s2, 8));
        t1 = addx2(t1, shfl_xor64(hi8 ? s1 : s3, 8));
        const bool hi4 = (lane & 4) != 0;
        ull r = hi4 ? t1 : t0;
        r = addx2(r, shfl_xor64(hi4 ? t0 : t1, 4));
        r = addx2(r, shfl_xor64(r, 2));
        r = addx2(r, shfl_xor64(r, 1));

        float v = 0.0f;
        if (outl) {
            const float s = (lane & 1) ? f2hi(r) : f2lo(r);
            v = tanhf(s + xpv);
        }
        xpv = xpn;

        // writers gather batches 1..3 (lanes +1, +4, +5 of same col)
        float vb1 = __shfl_down_sync(0xffffffffu, v, 1);
        float vb2 = __shfl_down_sync(0xffffffffu, v, 4);
        float vb3 = __shfl_down_sync(0xffffffffu, v, 5);

        if (t < SEQ - 1 && writer) {
            const int lc = 4 * grp + fcol;             // local col 0..63
            const uint32_t eoff =
                (uint32_t)((1 - p) * BUF_B +
                           (4 * rank + (lc >> 4)) * REG_STR + (lc & 15) * 16);
            const ull lo = pack2(v,   vb1);
            const ull hi = pack2(vb2, vb3);
            // local copy
            *(ull*)(hbuf + eoff)     = lo;
            *(ull*)(hbuf + eoff + 8) = hi;
            // push to all 7 peers (weak stores; ordered by the flag release)
            const uint32_t loff = hpb + eoff;
#pragma unroll
            for (int d = 1; d < RANKS; d++) {
                const int dst = (rank + d) & (RANKS - 1);
                st_cluster_u64(loff,     dst, lo);
                st_cluster_u64(loff + 8, dst, hi);
            }
        }

        // output store (overlaps data-store flight)
        if (outl) out[obase + (size_t)t * HID] = v;

        if (t < SEQ - 1) {
            __syncthreads();   // closes reads of buf p + orders all stores
            // publish "buf[1-p] for step t+1 is ready" to each peer
            if (grp >= 1 && grp <= 7 && lane == 0)
                st_release_flag(flb + (uint32_t)(rank * 4),
                                (rank + grp) & (RANKS - 1), (uint32_t)(t + 1));
        }
    }

    cluster_sync_();   // keep smem alive for slower peers' in-flight pushes
}

// ---------------------------------------------------------------------------
// Launch
// ---------------------------------------------------------------------------
extern "C" void kernel_launch(void* const* d_in, const int* in_sizes, int n_in,
                              void* d_out, int out_size) {
    const float* x_in = (const float*)d_in[0];
    const float* h0   = (const float*)d_in[1];
    const float* W_ih = (const float*)d_in[2];
    const float* W_hh = (const float*)d_in[3];
    const float* b_ih = (const float*)d_in[4];
    const float* b_hh = (const float*)d_in[5];
    float* out = (float*)d_out;

    dim3 gg((BATCH * SEQ) / BM, HID / BN);
    xproj_kernel<<<gg, 256>>>(x_in, W_ih, b_ih, b_hh, out);

    scan_kernel<<<(BATCH / BPC) * RANKS, 512>>>(h0, W_hh, out);
}

// round 17
// speedup vs baseline: 1.8252x; 1.8252x over previous
#include <cuda_runtime.h>
#include <math.h>
#include <stdint.h>

typedef unsigned long long ull;

#define BATCH 64
#define SEQ   2048
#define IN_F  256
#define HID   512
#define RANKS 8     // logical group: 8 CTAs share 4 batch rows
#define BPC   4     // batch rows per group

// 32 regions (one per k-lane) x 16 entries x 16B payload, stride 272 so the
// 32 lanes' concurrent reads are bank-conflict-free (bank = 4(lane+c) mod 32).
#define REG_STR   272
#define BUF_B     (32 * REG_STR)        // 8704 staging buffer

// ---------------------------------------------------------------------------
// Packed f32x2 helpers
// ---------------------------------------------------------------------------
__device__ __forceinline__ ull ffma2(ull a, ull b, ull c) {
    ull d;
    asm("fma.rn.f32x2 %0, %1, %2, %3;" : "=l"(d) : "l"(a), "l"(b), "l"(c));
    return d;
}
__device__ __forceinline__ ull addx2(ull a, ull b) {
    ull d;
    asm("add.rn.f32x2 %0, %1, %2;" : "=l"(d) : "l"(a), "l"(b));
    return d;
}
__device__ __forceinline__ ull dup2(float x) {
    ull d;
    asm("mov.b64 %0, {%1, %1};" : "=l"(d) : "f"(x));
    return d;
}
__device__ __forceinline__ ull pack2(float lo, float hi) {
    ull d;
    asm("mov.b64 %0, {%1, %2};" : "=l"(d) : "f"(lo), "f"(hi));
    return d;
}
__device__ __forceinline__ float f2lo(ull v) {
    return __int_as_float((int)(unsigned int)(v & 0xffffffffULL));
}
__device__ __forceinline__ float f2hi(ull v) {
    return __int_as_float((int)(unsigned int)(v >> 32));
}
__device__ __forceinline__ ull shfl_xor64(ull v, int m) {
    float lo = f2lo(v), hi = f2hi(v);
    lo = __shfl_xor_sync(0xffffffffu, lo, m);
    hi = __shfl_xor_sync(0xffffffffu, hi, m);
    return pack2(lo, hi);
}

// ---------------------------------------------------------------------------
// L2 flag transport (gpu-scope release/acquire; no clusters, no mbarriers)
// ---------------------------------------------------------------------------
// flags[(group*8 + rank) * 32]: monotonic step counter, 128B-padded.
__device__ uint32_t g_flags[16 * 8 * 32];

__device__ __forceinline__ void st_release_gpu_u32(uint32_t* p, uint32_t v) {
    asm volatile("st.release.gpu.global.u32 [%0], %1;" :: "l"(p), "r"(v) : "memory");
}
__device__ __forceinline__ uint32_t ld_acquire_gpu_u32(const uint32_t* p) {
    uint32_t v;
    asm volatile("ld.acquire.gpu.global.u32 %0, [%1];" : "=r"(v) : "l"(p) : "memory");
    return v;
}

// ---------------------------------------------------------------------------
// Kernel 1: x_proj GEMM  out[m][n] = sum_k X[m][k]*Wih[n][k] + bih[n] + bhh[n]
// Also resets the scan flags (runs before scan_kernel every launch).
// ---------------------------------------------------------------------------
#define BM 128
#define BN 64
#define BK 32
#define ASP 130

__global__ __launch_bounds__(256) void xproj_kernel(
    const float* __restrict__ X, const float* __restrict__ Wih,
    const float* __restrict__ bih, const float* __restrict__ bhh,
    float* __restrict__ out)
{
    __shared__ float As[BK][ASP];
    __shared__ float Ws[BK][BN];

    const int tid = threadIdx.x;

    // reset scan flags (one block is enough; scan launches after us)
    if (blockIdx.x == 0 && blockIdx.y == 0 && tid < 128)
        g_flags[tid * 32] = 0;

    const int m0 = blockIdx.x * BM;
    const int n0 = blockIdx.y * BN;
    const int tx = tid & 15;
    const int ty = tid >> 4;

    ull acc[4][4];
#pragma unroll
    for (int r = 0; r < 4; r++)
#pragma unroll
        for (int c = 0; c < 4; c++) acc[r][c] = 0ULL;

    for (int k0 = 0; k0 < IN_F; k0 += BK) {
#pragma unroll
        for (int i = 0; i < 4; i++) {
            int idx = tid + i * 256;
            int m = idx >> 3;
            int k4 = idx & 7;
            float4 v = *(const float4*)(X + (size_t)(m0 + m) * IN_F + k0 + k4 * 4);
            As[k4 * 4 + 0][m] = v.x;
            As[k4 * 4 + 1][m] = v.y;
            As[k4 * 4 + 2][m] = v.z;
            As[k4 * 4 + 3][m] = v.w;
        }
#pragma unroll
        for (int i = 0; i < 2; i++) {
            int idx = tid + i * 256;
            int n = idx >> 3;
            int k4 = idx & 7;
            float4 v = *(const float4*)(Wih + (size_t)(n0 + n) * IN_F + k0 + k4 * 4);
            Ws[k4 * 4 + 0][n] = v.x;
            Ws[k4 * 4 + 1][n] = v.y;
            Ws[k4 * 4 + 2][n] = v.z;
            Ws[k4 * 4 + 3][n] = v.w;
        }
        __syncthreads();

#pragma unroll
        for (int k = 0; k < BK; k++) {
            ull ap[4];
#pragma unroll
            for (int r = 0; r < 4; r++)
                ap[r] = *(const ull*)&As[k][ty * 8 + 2 * r];
            float4 wv = *(const float4*)&Ws[k][tx * 4];
            ull wd0 = dup2(wv.x), wd1 = dup2(wv.y);
            ull wd2 = dup2(wv.z), wd3 = dup2(wv.w);
#pragma unroll
            for (int r = 0; r < 4; r++) {
                acc[r][0] = ffma2(ap[r], wd0, acc[r][0]);
                acc[r][1] = ffma2(ap[r], wd1, acc[r][1]);
                acc[r][2] = ffma2(ap[r], wd2, acc[r][2]);
                acc[r][3] = ffma2(ap[r], wd3, acc[r][3]);
            }
        }
        __syncthreads();
    }

    float bsum[4];
#pragma unroll
    for (int c = 0; c < 4; c++) {
        int n = n0 + tx * 4 + c;
        bsum[c] = bih[n] + bhh[n];
    }
#pragma unroll
    for (int r = 0; r < 4; r++) {
        size_t mlo = (size_t)(m0 + ty * 8 + 2 * r);
        float4 lo4, hi4;
        lo4.x = f2lo(acc[r][0]) + bsum[0]; lo4.y = f2lo(acc[r][1]) + bsum[1];
        lo4.z = f2lo(acc[r][2]) + bsum[2]; lo4.w = f2lo(acc[r][3]) + bsum[3];
        hi4.x = f2hi(acc[r][0]) + bsum[0]; hi4.y = f2hi(acc[r][1]) + bsum[1];
        hi4.z = f2hi(acc[r][2]) + bsum[2]; hi4.w = f2hi(acc[r][3]) + bsum[3];
        *(float4*)(out + mlo * HID + n0 + tx * 4)       = lo4;
        *(float4*)(out + (mlo + 1) * HID + n0 + tx * 4) = hi4;
    }
}

// ---------------------------------------------------------------------------
// Kernel 2: scan with L2-routed h exchange — NO clusters, NO DSMEM.
//
// 128 plain CTAs; logical group g = blockIdx>>3 owns batch rows [4g,4g+4);
// rank = blockIdx&7 owns output columns [64r, 64r+64). W slice in registers
// (R14 layout: warp grp owns 4 cols; lane = k-chunk of 16).
//
// h(t) lives in `out` itself: out[b][t][col] is written exactly once, so the
// sequence index doubles as the exchange buffer index — no double buffering,
// no overwrite hazard. Per step:
//   publish:  STG h values to out row t  -> __syncthreads ->
//             tid0 st.release.gpu g_flags[group][rank] = t+1
//   receive:  warp0 polls the 7 peer flags (ld.acquire.gpu + ballot) >= t,
//             bar, all 512 threads restage out row t-1 (64 coalesced lines,
//             L2-hot) into conflict-free smem regions, bar, compute (R14
//             body: 16 LDS.128/thread, value-splitting butterfly).
// ---------------------------------------------------------------------------
__global__ void __launch_bounds__(512, 1)
scan_kernel(const float* __restrict__ h0, const float* __restrict__ Whh,
            float* __restrict__ out)
{
    __shared__ __align__(16) char hbuf[BUF_B];

    const int tid  = threadIdx.x;
    const int lane = tid & 31;                 // k-chunk index
    const int grp  = tid >> 5;                 // warp id = column group
    const int rank = blockIdx.x & (RANKS - 1);
    const int gid  = blockIdx.x >> 3;          // logical group (batch set)
    const int b0   = gid * BPC;
    const int gcol0 = rank * 64 + 4 * grp;     // first of our 4 columns

    // ---- W slices: 4 cols x 16 ks
    float w[4][16];
#pragma unroll
    for (int c = 0; c < 4; c++) {
        const float* wr = Whh + (size_t)(gcol0 + c) * HID + lane * 16;
#pragma unroll
        for (int j4 = 0; j4 < 4; j4++) {
            float4 a = *(const float4*)(wr + j4 * 4);
            w[c][4*j4+0] = a.x; w[c][4*j4+1] = a.y;
            w[c][4*j4+2] = a.z; w[c][4*j4+3] = a.w;
        }
    }

    // ---- preload h0 into staging (k = tid)
    {
        const int k = tid;
        float v0 = h0[(size_t)(b0 + 0) * HID + k];
        float v1 = h0[(size_t)(b0 + 1) * HID + k];
        float v2 = h0[(size_t)(b0 + 2) * HID + k];
        float v3 = h0[(size_t)(b0 + 3) * HID + k];
        char* e = hbuf + (k >> 4) * REG_STR + (k & 15) * 16;
        *(ull*)e       = pack2(v0, v1);
        *(ull*)(e + 8) = pack2(v2, v3);
    }
    __syncthreads();

    // final-lane roles (after butterfly)
    const int  fcol = (lane >> 3) & 3;              // col within group
    const int  fbp  = (lane >> 2) & 1;              // batch pair
    const bool outl = (lane & 2) == 0;
    const int  obat = 2 * fbp + (lane & 1);
    const size_t obase = outl
        ? (((size_t)(b0 + obat) * SEQ) * HID + gcol0 + fcol) : 0;
    float xpv = outl ? out[obase] : 0.0f;

    // poll role: warp 0, lanes 0..7 (skip own rank)
    const bool pollme = (grp == 0) && (lane < 8) && (lane != rank);
    uint32_t* const myflag = &g_flags[(gid * 8 + lane) * 32];
    uint32_t* const ourflag = &g_flags[(gid * 8 + rank) * 32];

    // precomputed staging source offsets (k = tid, 4 batch rows)
    const size_t srow0 = ((size_t)(b0 + 0) * SEQ) * HID + tid;
    const size_t srow1 = ((size_t)(b0 + 1) * SEQ) * HID + tid;
    const size_t srow2 = ((size_t)(b0 + 2) * SEQ) * HID + tid;
    const size_t srow3 = ((size_t)(b0 + 3) * SEQ) * HID + tid;
    char* const sentry = hbuf + (tid >> 4) * REG_STR + (tid & 15) * 16;

    for (int t = 0; t < SEQ; t++) {
        if (t) {
            // ---- wait for all 7 peers to have published row t-1
            if (grp == 0) {
                const uint32_t tt = (uint32_t)t;
                for (;;) {
                    uint32_t f = 0xffffffffu;
                    if (pollme) f = ld_acquire_gpu_u32(myflag);
                    if (__all_sync(0xffffffffu, f >= tt)) break;
                }
            }
            __syncthreads();            // poll done -> row t-1 readable
            // ---- restage h(t-1) from out row t-1 (coalesced, L2-hot)
            {
                const size_t ro = (size_t)(t - 1) * HID;
                float v0 = out[srow0 + ro];
                float v1 = out[srow1 + ro];
                float v2 = out[srow2 + ro];
                float v3 = out[srow3 + ro];
                *(ull*)sentry       = pack2(v0, v1);
                *(ull*)(sentry + 8) = pack2(v2, v3);
            }
            __syncthreads();            // staging visible to all warps
        }

        const ulonglong2* hreg =
            (const ulonglong2*)(hbuf + lane * REG_STR);
        ull a01[4] = {0, 0, 0, 0};
        ull a23[4] = {0, 0, 0, 0};
#pragma unroll
        for (int j = 0; j < 16; j++) {
            ulonglong2 e = hreg[j];
#pragma unroll
            for (int c = 0; c < 4; c++) {
                ull wd = dup2(w[c][j]);
                a01[c] = ffma2(wd, e.x, a01[c]);
                a23[c] = ffma2(wd, e.y, a23[c]);
            }
        }

        // prefetch next step's xp while reduction runs
        float xpn = 0.0f;
        if (outl && t + 1 < SEQ) xpn = out[obase + (size_t)(t + 1) * HID];

        // ---- value-splitting butterfly over the full warp
        const bool hi16 = (lane & 16) != 0;
        ull s0 = hi16 ? a01[2] : a01[0];
        ull s1 = hi16 ? a23[2] : a23[0];
        ull s2 = hi16 ? a01[3] : a01[1];
        ull s3 = hi16 ? a23[3] : a23[1];
        s0 = addx2(s0, shfl_xor64(hi16 ? a01[0] : a01[2], 16));
        s1 = addx2(s1, shfl_xor64(hi16 ? a23[0] : a23[2], 16));
        s2 = addx2(s2, shfl_xor64(hi16 ? a01[1] : a01[3], 16));
        s3 = addx2(s3, shfl_xor64(hi16 ? a23[1] : a23[3], 16));
        const bool hi8 = (lane & 8) != 0;
        ull t0 = hi8 ? s2 : s0;
        ull t1 = hi8 ? s3 : s1;
        t0 = addx2(t0, shfl_xor64(hi8 ? s0 : s2, 8));
        t1 = addx2(t1, shfl_xor64(hi8 ? s1 : s3, 8));
        const bool hi4 = (lane & 4) != 0;
        ull r = hi4 ? t1 : t0;
        r = addx2(r, shfl_xor64(hi4 ? t0 : t1, 4));
        r = addx2(r, shfl_xor64(r, 2));
        r = addx2(r, shfl_xor64(r, 1));

        float v = 0.0f;
        if (outl) {
            const float s = (lane & 1) ? f2hi(r) : f2lo(r);
            v = tanhf(s + xpv);
            out[obase + (size_t)t * HID] = v;   // publish h(t)
        }
        xpv = xpn;

        if (t < SEQ - 1) {
            __syncthreads();            // all STGs happen-before the release
            if (tid == 0) st_release_gpu_u32(ourflag, (uint32_t)(t + 1));
        }
    }
}

// ---------------------------------------------------------------------------
// Launch
// ---------------------------------------------------------------------------
extern "C" void kernel_launch(void* const* d_in, const int* in_sizes, int n_in,
                              void* d_out, int out_size) {
    const float* x_in = (const float*)d_in[0];
    const float* h0   = (const float*)d_in[1];
    const float* W_ih = (const float*)d_in[2];
    const float* W_hh = (const float*)d_in[3];
    const float* b_ih = (const float*)d_in[4];
    const float* b_hh = (const float*)d_in[5];
    float* out = (float*)d_out;

    dim3 gg((BATCH * SEQ) / BM, HID / BN);
    xproj_kernel<<<gg, 256>>>(x_in, W_ih, b_ih, b_hh, out);

    scan_kernel<<<(BATCH / BPC) * RANKS, 512>>>(h0, W_hh, out);
}